// round 1
// baseline (speedup 1.0000x reference)
#include <cuda_runtime.h>

// Problem constants (fixed by the reference)
#define HID   51
#define NROWS 204        // 4*HID gate rows
#define NSEQ  8          // sequences per block
#define TT    2048
#define NN    1024
#define CHUNK 64         // time steps staged per shared-memory chunk
#define HPAD  64         // padded h row stride (floats)
#define KP    26         // packed k pairs (covers 52, last padded with 0)

typedef unsigned long long u64;

__device__ __forceinline__ u64 pack2(float lo, float hi) {
    u64 r; asm("mov.b64 %0, {%1,%2};" : "=l"(r) : "f"(lo), "f"(hi)); return r;
}
__device__ __forceinline__ void unpack2(u64 v, float& lo, float& hi) {
    asm("mov.b64 {%0,%1}, %2;" : "=f"(lo), "=f"(hi) : "l"(v));
}
// Blackwell packed fp32 FMA: 2 MACs per instruction, full fp32 precision.
__device__ __forceinline__ u64 fma2(u64 a, u64 b, u64 c) {
    u64 d; asm("fma.rn.f32x2 %0, %1, %2, %3;" : "=l"(d) : "l"(a), "l"(b), "l"(c));
    return d;
}

// Fast, safe activations (MUFU EX2 + RCP; per-op error ~1e-6, well under 1e-3 budget)
__device__ __forceinline__ float sigm(float x) {
    float e = __expf(-x);
    return __fdividef(1.0f, 1.0f + e);
}
__device__ __forceinline__ float tanh_(float x) {
    float ax = fabsf(x);
    float e  = __expf(-2.0f * ax);             // in (0,1], never overflows
    float r  = __fdividef(1.0f - e, 1.0f + e);
    return (x < 0.0f) ? -r : r;
}

__global__ void __launch_bounds__(224, 1)
lstm2_kernel(const float* __restrict__ stim,
             const float* __restrict__ Wih1,   // (204,1)
             const float* __restrict__ Whh1,   // (204,51)
             const float* __restrict__ bih1,   // (204)
             const float* __restrict__ bhh1,   // (204)
             const float* __restrict__ Wih2,   // (4,51)
             const float* __restrict__ Whh2,   // (4,1)
             const float* __restrict__ bih2,   // (4)
             const float* __restrict__ bhh2,   // (4)
             float* __restrict__ out)          // (1024,2048)
{
    __shared__ __align__(16) float h1_sh[NSEQ][HPAD];   // layer-1 hidden state (padded, [51..63]=0)
    __shared__ __align__(16) float act_sh[NROWS][NSEQ]; // activated gates
    __shared__ __align__(16) float x_sh[NSEQ][CHUNK];   // staged stimulus chunk
    __shared__ __align__(16) float ob_sh[NSEQ][CHUNK];  // staged output chunk
    __shared__ __align__(16) float w2_sh[4][56];        // layer-2 W_ih2, k-padded to 52 (rest 0)
    __shared__ float b2_sh[4];
    __shared__ float whh2_sh[4];

    const int tid  = threadIdx.x;
    const int wid  = tid >> 5;
    const int lane = tid & 31;
    const int n0   = blockIdx.x * NSEQ;

    // ---- one-time setup -------------------------------------------------
    u64   wreg[KP];            // this thread's W_hh1 row, k-packed (f32x2 pairs)
    float bias1 = 0.f, wi1 = 0.f;
    if (tid < NROWS) {
        const float* wr = Whh1 + tid * HID;
#pragma unroll
        for (int kk = 0; kk < KP; kk++) {
            float a = (2*kk   < HID) ? wr[2*kk]   : 0.f;
            float b = (2*kk+1 < HID) ? wr[2*kk+1] : 0.f;
            wreg[kk] = pack2(a, b);
        }
        bias1 = bih1[tid] + bhh1[tid];
        wi1   = Wih1[tid];
    }
    if (tid < 4) { b2_sh[tid] = bih2[tid] + bhh2[tid]; whh2_sh[tid] = Whh2[tid]; }
    for (int i = tid; i < 4 * 56; i += blockDim.x) {
        int g = i / 56, k = i % 56;
        w2_sh[g][k] = (k < HID) ? Wih2[g * HID + k] : 0.f;
    }
    for (int i = tid; i < NSEQ * HPAD; i += blockDim.x)
        ((float*)h1_sh)[i] = 0.f;   // h1 = 0 (padding stays 0 forever)

    // phase-B cell state: thread (tid<204) owns hidden j=tid%51 for seqs s0=tid/51 and s0+4
    float c1a = 0.f, c1b = 0.f;
    // layer-2 state (warp 3, replicated across the 4 lanes of each seq-group)
    float c2 = 0.f, h2 = 0.f;

    __syncthreads();

    // ---- main recurrence ------------------------------------------------
    for (int t0 = 0; t0 < TT; t0 += CHUNK) {
        __syncthreads();  // orders last chunk's phase-C ob_sh writes before flush
        if (tid < 128) {
            int s = tid >> 4, q = (tid & 15) * 4;
            if (t0 > 0)
                *(float4*)&out[(n0 + s) * TT + (t0 - CHUNK) + q] =
                    *(const float4*)&ob_sh[s][q];
            *(float4*)&x_sh[s][q] =
                *(const float4*)&stim[(n0 + s) * TT + t0 + q];
        }
        __syncthreads();

        for (int dt = 0; dt < CHUNK; dt++) {
            // -------- phase A: layer-1 gates (204 threads, FMA2 matvec) --
            if (tid < NROWS) {
                u64 acc[NSEQ];
#pragma unroll
                for (int s = 0; s < NSEQ; s++) {
                    float xv = x_sh[s][dt];
                    acc[s] = pack2(fmaf(wi1, xv, bias1), 0.f);
                }
#pragma unroll
                for (int kk = 0; kk < KP / 2; kk++) {       // 13 iters
#pragma unroll
                    for (int s = 0; s < NSEQ; s++) {        // ILP across 8 accs
                        ulonglong2 hv =
                            ((const ulonglong2*)&h1_sh[s][0])[kk]; // LDS.128 broadcast
                        acc[s] = fma2(wreg[2*kk],   hv.x, acc[s]);
                        acc[s] = fma2(wreg[2*kk+1], hv.y, acc[s]);
                    }
                }
                const bool is_sig = (tid < 2 * HID) || (tid >= 3 * HID); // i,f,o
                float av[NSEQ];
#pragma unroll
                for (int s = 0; s < NSEQ; s++) {
                    float lo, hi; unpack2(acc[s], lo, hi);
                    float g = lo + hi;
                    av[s] = is_sig ? sigm(g) : tanh_(g);
                }
                *(float4*)&act_sh[tid][0] = make_float4(av[0], av[1], av[2], av[3]);
                *(float4*)&act_sh[tid][4] = make_float4(av[4], av[5], av[6], av[7]);
            }
            __syncthreads();

            // -------- phase B: cell/hidden update (2 (j,s) tasks/thread) --
            if (tid < NROWS) {
                const int j  = tid % HID;
                const int s0 = tid / HID;       // 0..3
                {
                    float ai = act_sh[j][s0],        af = act_sh[j + HID][s0];
                    float ag = act_sh[j + 2*HID][s0], ao = act_sh[j + 3*HID][s0];
                    c1a = fmaf(af, c1a, ai * ag);
                    h1_sh[s0][j] = ao * tanh_(c1a);
                }
                {
                    const int s1 = s0 + 4;
                    float ai = act_sh[j][s1],        af = act_sh[j + HID][s1];
                    float ag = act_sh[j + 2*HID][s1], ao = act_sh[j + 3*HID][s1];
                    c1b = fmaf(af, c1b, ai * ag);
                    h1_sh[s1][j] = ao * tanh_(c1b);
                }
            }
            __syncthreads();

            // -------- phase C: layer 2 (warp 3 only — alone on its SMSP,
            //          overlaps other warps' phase A of the next step) -----
            if (wid == 3) {
                const int s = lane >> 2, g = lane & 3;
                u64 a2 = pack2(fmaf(whh2_sh[g], h2, b2_sh[g]), 0.f);
#pragma unroll
                for (int q = 0; q < 13; q++) {              // k = 0..51
                    ulonglong2 hv = *(const ulonglong2*)&h1_sh[s][4 * q];
                    ulonglong2 wv = *(const ulonglong2*)&w2_sh[g][4 * q];
                    a2 = fma2(wv.x, hv.x, a2);
                    a2 = fma2(wv.y, hv.y, a2);
                }
                float lo, hi; unpack2(a2, lo, hi);
                float gate = lo + hi;
                const unsigned base = lane & ~3u;
                float gi = __shfl_sync(0xFFFFFFFFu, gate, base);
                float gf = __shfl_sync(0xFFFFFFFFu, gate, base + 1);
                float gg = __shfl_sync(0xFFFFFFFFu, gate, base + 2);
                float go = __shfl_sync(0xFFFFFFFFu, gate, base + 3);
                c2 = fmaf(sigm(gf), c2, sigm(gi) * tanh_(gg));  // redundant per 4 lanes
                h2 = sigm(go) * tanh_(c2);
                if (g == 0) ob_sh[s][dt] = h2;
            }
            // no barrier here: phase A(t+1) only reads h1_sh/x_sh; warp 3
            // re-joins at the next __syncthreads before anyone writes them.
        }
    }

    // final output flush
    __syncthreads();
    if (tid < 128) {
        int s = tid >> 4, q = (tid & 15) * 4;
        *(float4*)&out[(n0 + s) * TT + (TT - CHUNK) + q] =
            *(const float4*)&ob_sh[s][q];
    }
}

extern "C" void kernel_launch(void* const* d_in, const int* in_sizes, int n_in,
                              void* d_out, int out_size)
{
    (void)in_sizes; (void)n_in; (void)out_size;
    const float* stim  = (const float*)d_in[0];
    const float* Wih1  = (const float*)d_in[1];
    const float* Whh1  = (const float*)d_in[2];
    const float* bih1  = (const float*)d_in[3];
    const float* bhh1  = (const float*)d_in[4];
    const float* Wih2  = (const float*)d_in[5];
    const float* Whh2  = (const float*)d_in[6];
    const float* bih2  = (const float*)d_in[7];
    const float* bhh2  = (const float*)d_in[8];
    float* out = (float*)d_out;

    lstm2_kernel<<<NN / NSEQ, 224>>>(stim, Wih1, Whh1, bih1, bhh1,
                                     Wih2, Whh2, bih2, bhh2, out);
}

// round 2
// speedup vs baseline: 1.2409x; 1.2409x over previous
#include <cuda_runtime.h>

// Problem constants (fixed by the reference)
#define HID   51
#define NROWS 204
#define NSEQ  4          // sequences per block -> grid = 256, 2 blocks/SM
#define TT    2048
#define NN    1024
#define CHUNK 64
#define HPAD  68         // padded h row stride (floats); 272B = 17*16B -> bank-staggered
#define KP    26         // packed k pairs (covers 52, last lane padded with 0)
#define NTHREADS 256

typedef unsigned long long u64;

__device__ __forceinline__ u64 pack2(float lo, float hi) {
    u64 r; asm("mov.b64 %0, {%1,%2};" : "=l"(r) : "f"(lo), "f"(hi)); return r;
}
__device__ __forceinline__ void unpack2(u64 v, float& lo, float& hi) {
    asm("mov.b64 {%0,%1}, %2;" : "=f"(lo), "=f"(hi) : "l"(v));
}
// Blackwell packed fp32 FMA: 2 MACs per instruction, full fp32 precision.
__device__ __forceinline__ u64 fma2(u64 a, u64 b, u64 c) {
    u64 d; asm("fma.rn.f32x2 %0, %1, %2, %3;" : "=l"(d) : "l"(a), "l"(b), "l"(c));
    return d;
}

__device__ __forceinline__ float sigm(float x) {
    float e = __expf(-x);
    return __fdividef(1.0f, 1.0f + e);
}
__device__ __forceinline__ float tanh_(float x) {
    float ax = fabsf(x);
    float e  = __expf(-2.0f * ax);
    float r  = __fdividef(1.0f - e, 1.0f + e);
    return (x < 0.0f) ? -r : r;
}

__global__ void __launch_bounds__(NTHREADS, 2)
lstm2_kernel(const float* __restrict__ stim,
             const float* __restrict__ Wih1,   // (204,1)
             const float* __restrict__ Whh1,   // (204,51)
             const float* __restrict__ bih1,
             const float* __restrict__ bhh1,
             const float* __restrict__ Wih2,   // (4,51)
             const float* __restrict__ Whh2,   // (4,1)
             const float* __restrict__ bih2,
             const float* __restrict__ bhh2,
             float* __restrict__ out)          // (1024,2048)
{
    __shared__ __align__(16) float hbuf[2][NSEQ][HPAD]; // ping-pong h1 (pads stay 0)
    __shared__ __align__(16) float x_sh[NSEQ][CHUNK];
    __shared__ __align__(16) float ob_sh[NSEQ][CHUNK];

    const int tid  = threadIdx.x;
    const int wid  = tid >> 5;
    const int lane = tid & 31;
    const int jj   = lane & 7;
    const int g    = lane >> 3;        // gate index 0..3 (i,f,g,o)
    const int j    = wid * 8 + jj;     // hidden index (valid if < 51)
    const int n0   = blockIdx.x * NSEQ;

    const bool mv     = (wid < 7);                 // matvec warps
    const bool l2lane = (wid == 7) && (lane < 16); // layer-2 lanes
    const int  s2 = lane >> 2;                     // 0..3 (layer-2 seq)
    const int  g2 = lane & 3;                      // 0..3 (layer-2 gate)

    // ---- per-lane weights in registers ---------------------------------
    u64 wreg[KP];
#pragma unroll
    for (int kk = 0; kk < KP; kk++) wreg[kk] = 0ull;
    float bias1 = 0.f, wi1 = 0.f;

    if (mv && j < HID) {
        const int row = g * HID + j;
        const float* wr = Whh1 + row * HID;
#pragma unroll
        for (int kk = 0; kk < KP; kk++) {
            float a = (2*kk   < HID) ? wr[2*kk]   : 0.f;
            float b = (2*kk+1 < HID) ? wr[2*kk+1] : 0.f;
            wreg[kk] = pack2(a, b);
        }
        bias1 = bih1[row] + bhh1[row];
        wi1   = Wih1[row];
    } else if (l2lane) {
        const float* wr = Wih2 + g2 * HID;         // reuse wreg for layer-2 row
#pragma unroll
        for (int kk = 0; kk < KP; kk++) {
            float a = (2*kk   < HID) ? wr[2*kk]   : 0.f;
            float b = (2*kk+1 < HID) ? wr[2*kk+1] : 0.f;
            wreg[kk] = pack2(a, b);
        }
        bias1 = bih2[g2] + bhh2[g2];
        wi1   = Whh2[g2];
    }

    for (int i = tid; i < 2 * NSEQ * HPAD; i += NTHREADS)
        ((float*)hbuf)[i] = 0.f;

    float c1[NSEQ];
#pragma unroll
    for (int s = 0; s < NSEQ; s++) c1[s] = 0.f;
    float h2 = 0.f, c2 = 0.f;

    // layer-2 step: processes h1 sitting in hbuf[rd], writes ob_sh[s2][idx]
    auto layer2 = [&](int rd, int idx) {
        u64 a2 = pack2(fmaf(wi1, h2, bias1), 0.f);
        const ulonglong2* hp = (const ulonglong2*)&hbuf[rd][s2][0];
#pragma unroll
        for (int q = 0; q < KP / 2; q++) {
            ulonglong2 hv = hp[q];
            a2 = fma2(wreg[2*q],   hv.x, a2);
            a2 = fma2(wreg[2*q+1], hv.y, a2);
        }
        float lo, hi; unpack2(a2, lo, hi);
        float gate = lo + hi;
        const unsigned base = lane & ~3u;
        float gi = __shfl_sync(0xFFFFu, gate, base);
        float gf = __shfl_sync(0xFFFFu, gate, base + 1);
        float gg = __shfl_sync(0xFFFFu, gate, base + 2);
        float go = __shfl_sync(0xFFFFu, gate, base + 3);
        c2 = fmaf(sigm(gf), c2, sigm(gi) * tanh_(gg));
        h2 = sigm(go) * tanh_(c2);
        if (g2 == 0) ob_sh[s2][idx] = h2;
    };

    __syncthreads();

#pragma unroll 1
    for (int t0 = 0; t0 < TT; t0 += CHUNK) {
        // layer-2 catch-up for time t0-1 (h1(t0-1) lives in hbuf[0])
        if (t0 > 0 && l2lane) layer2(0, CHUNK - 1);
        __syncthreads();
        if (tid < 64) {
            int s = tid >> 4, q = (tid & 15) * 4;
            if (t0 > 0)
                *(float4*)&out[(n0 + s) * TT + (t0 - CHUNK) + q] =
                    *(const float4*)&ob_sh[s][q];
            *(float4*)&x_sh[s][q] =
                *(const float4*)&stim[(n0 + s) * TT + t0 + q];
        }
        __syncthreads();

#pragma unroll 1
        for (int dt = 0; dt < CHUNK; dt++) {
            const int rd = dt & 1;          // read buffer; write = 1-rd
            if (mv) {
                u64 acc[NSEQ];
#pragma unroll
                for (int s = 0; s < NSEQ; s++)
                    acc[s] = pack2(fmaf(wi1, x_sh[s][dt], bias1), 0.f);
#pragma unroll
                for (int kk = 0; kk < KP / 2; kk++) {
#pragma unroll
                    for (int s = 0; s < NSEQ; s++) {
                        ulonglong2 hv =
                            ((const ulonglong2*)&hbuf[rd][s][0])[kk]; // broadcast
                        acc[s] = fma2(wreg[2*kk],   hv.x, acc[s]);
                        acc[s] = fma2(wreg[2*kk+1], hv.y, acc[s]);
                    }
                }
                const bool istanh = (g == 2);
                float av[NSEQ];
#pragma unroll
                for (int s = 0; s < NSEQ; s++) {
                    float lo, hi; unpack2(acc[s], lo, hi);
                    float gt = lo + hi;
                    av[s] = istanh ? tanh_(gt) : sigm(gt);
                }
                // in-warp gate gather: lane g*8+jj -> gate-0 lane updates cell
#pragma unroll
                for (int s = 0; s < NSEQ; s++) {
                    float af = __shfl_down_sync(0xFFFFFFFFu, av[s], 8);
                    float ag = __shfl_down_sync(0xFFFFFFFFu, av[s], 16);
                    float ao = __shfl_down_sync(0xFFFFFFFFu, av[s], 24);
                    if (g == 0 && j < HID) {
                        c1[s] = fmaf(af, c1[s], av[s] * ag);
                        hbuf[1 - rd][s][j] = ao * tanh_(c1[s]);
                    }
                }
            } else if (l2lane && dt > 0) {
                layer2(rd, dt - 1);         // time t0+dt-1
            }
            __syncthreads();
        }
    }

    // final step's layer-2 (h1(2047) is in hbuf[0]) + last flush
    if (l2lane) layer2(0, CHUNK - 1);
    __syncthreads();
    if (tid < 64) {
        int s = tid >> 4, q = (tid & 15) * 4;
        *(float4*)&out[(n0 + s) * TT + (TT - CHUNK) + q] =
            *(const float4*)&ob_sh[s][q];
    }
}

extern "C" void kernel_launch(void* const* d_in, const int* in_sizes, int n_in,
                              void* d_out, int out_size)
{
    (void)in_sizes; (void)n_in; (void)out_size;
    const float* stim  = (const float*)d_in[0];
    const float* Wih1  = (const float*)d_in[1];
    const float* Whh1  = (const float*)d_in[2];
    const float* bih1  = (const float*)d_in[3];
    const float* bhh1  = (const float*)d_in[4];
    const float* Wih2  = (const float*)d_in[5];
    const float* Whh2  = (const float*)d_in[6];
    const float* bih2  = (const float*)d_in[7];
    const float* bhh2  = (const float*)d_in[8];
    float* out = (float*)d_out;

    lstm2_kernel<<<NN / NSEQ, NTHREADS>>>(stim, Wih1, Whh1, bih1, bhh1,
                                          Wih2, Whh2, bih2, bhh2, out);
}

// round 3
// speedup vs baseline: 1.6920x; 1.3635x over previous
#include <cuda_runtime.h>

#define HID   51
#define NSEQ  4
#define TT    2048
#define NN    1024
#define CHUNK 64
#define HPAD  56         // padded h row (floats), reads reach index 51
#define KP    26         // k pairs (51 cols + zero pad)
#define NTHREADS 256     // 8 warps

typedef unsigned long long u64;

__device__ __forceinline__ u64 pack2(float lo, float hi) {
    u64 r; asm("mov.b64 %0, {%1,%2};" : "=l"(r) : "f"(lo), "f"(hi)); return r;
}
__device__ __forceinline__ void unpack2(u64 v, float& lo, float& hi) {
    asm("mov.b64 {%0,%1}, %2;" : "=f"(lo), "=f"(hi) : "l"(v));
}
__device__ __forceinline__ u64 fma2(u64 a, u64 b, u64 c) {
    u64 d; asm("fma.rn.f32x2 %0, %1, %2, %3;" : "=l"(d) : "l"(a), "l"(b), "l"(c));
    return d;
}
__device__ __forceinline__ float ex2f(float x) {
    float r; asm("ex2.approx.ftz.f32 %0, %1;" : "=f"(r) : "f"(x)); return r;
}
__device__ __forceinline__ float rcpf(float x) {
    float r; asm("rcp.approx.ftz.f32 %0, %1;" : "=f"(r) : "f"(x)); return r;
}

#define L2E  1.4426950408889634f
// tanh(x) = 1 - 2/(e^{2x}+1)  (saturates correctly at +/-inf)
__device__ __forceinline__ float tanh_u(float x) {
    return fmaf(-2.0f, rcpf(ex2f(2.0f * L2E * x) + 1.0f), 1.0f);
}

__global__ void __launch_bounds__(NTHREADS, 2)
lstm2_kernel(const float* __restrict__ stim,
             const float* __restrict__ Wih1,   // (204,1)
             const float* __restrict__ Whh1,   // (204,51)
             const float* __restrict__ bih1,
             const float* __restrict__ bhh1,
             const float* __restrict__ Wih2,   // (4,51)
             const float* __restrict__ Whh2,   // (4,1)
             const float* __restrict__ bih2,
             const float* __restrict__ bhh2,
             float* __restrict__ out)          // (1024,2048)
{
    __shared__ __align__(16) float hbuf[2][NSEQ][HPAD];
    __shared__ __align__(16) float x_sh[CHUNK][NSEQ];   // transposed: [dt][s]
    __shared__ __align__(16) float ob_sh[NSEQ][CHUNK];  // [s][dt] = y(t0+dt-1)

    const int tid  = threadIdx.x;
    const int wid  = tid >> 5;
    const int lane = tid & 31;
    const int jj   = lane & 7;
    const int g    = lane >> 3;        // gate 0..3 (i,f,g,o)
    const int j    = wid * 7 + jj;     // hidden row index; j==51 => layer-2 rows
    const int n0   = blockIdx.x * NSEQ;
    const bool active = (jj < 7) && (j <= HID);   // j in [0,51]
    const bool isl2   = (j == HID);               // layer-2 gate rows

    // ---- per-lane weights in registers ---------------------------------
    u64 wreg[KP];
#pragma unroll
    for (int kk = 0; kk < KP; kk++) wreg[kk] = 0ull;
    float bias = 0.f, wi = 0.f;
    if (active) {
        const float* wr = isl2 ? (Wih2 + g * HID)
                               : (Whh1 + (g * HID + j) * HID);
#pragma unroll
        for (int kk = 0; kk < KP; kk++) {
            float a = wr[2*kk];
            float b = (2*kk + 1 < HID) ? wr[2*kk + 1] : 0.f;
            wreg[kk] = pack2(a, b);
        }
        if (isl2) { bias = bih2[g] + bhh2[g]; wi = Whh2[g]; }
        else      { bias = bih1[g*HID + j] + bhh1[g*HID + j]; wi = Wih1[g*HID + j]; }
    }
    // unified activation constants: sigmoid (g!=2) / tanh (g==2)
    const float aC = (g == 2) ? 2.0f * L2E : -L2E;
    const float aB = (g == 2) ? -2.0f : 1.0f;
    const float aA = (g == 2) ?  1.0f : 0.0f;

    for (int i = tid; i < 2 * NSEQ * HPAD; i += NTHREADS)
        ((float*)hbuf)[i] = 0.f;

    float cst[NSEQ];                   // c1 for j<51 lanes; c2 for j==51 lane
#pragma unroll
    for (int s = 0; s < NSEQ; s++) cst[s] = 0.f;
    float h2b[NSEQ];                   // h2 state, replicated across warp 7
#pragma unroll
    for (int s = 0; s < NSEQ; s++) h2b[s] = 0.f;

    // stage chunk 0 stimulus (transposed)
    if (tid < 64) {
        int s = tid >> 4, q = (tid & 15) * 4;
        float4 v = *(const float4*)&stim[(n0 + s) * TT + q];
        x_sh[q + 0][s] = v.x; x_sh[q + 1][s] = v.y;
        x_sh[q + 2][s] = v.z; x_sh[q + 3][s] = v.w;
    }
    __syncthreads();

#pragma unroll 1
    for (int t0 = 0; t0 < TT; t0 += CHUNK) {
#pragma unroll 2
        for (int dt = 0; dt < CHUNK; dt++) {
            const int rd = dt & 1;
            // ---- matvec: 4 accs over k-pairs (FMA2) --------------------
            float4 xv = *(const float4*)&x_sh[dt][0];
            float xin[NSEQ] = {xv.x, xv.y, xv.z, xv.w};
            if (isl2) {
#pragma unroll
                for (int s = 0; s < NSEQ; s++) xin[s] = h2b[s];
            }
            u64 acc[NSEQ];
#pragma unroll
            for (int s = 0; s < NSEQ; s++)
                acc[s] = pack2(fmaf(wi, xin[s], bias), 0.f);
#pragma unroll
            for (int kk = 0; kk < KP / 2; kk++) {
#pragma unroll
                for (int s = 0; s < NSEQ; s++) {
                    ulonglong2 hv = ((const ulonglong2*)&hbuf[rd][s][0])[kk];
                    acc[s] = fma2(wreg[2*kk],   hv.x, acc[s]);
                    acc[s] = fma2(wreg[2*kk+1], hv.y, acc[s]);
                }
            }
            // ---- activation (branch-free) ------------------------------
            float av[NSEQ];
#pragma unroll
            for (int s = 0; s < NSEQ; s++) {
                float lo, hi; unpack2(acc[s], lo, hi);
                float gt = lo + hi;
                av[s] = fmaf(aB, rcpf(ex2f(gt * aC) + 1.0f), aA);
            }
            // ---- gate exchange + cell update ---------------------------
            float af[NSEQ], ag[NSEQ], ao[NSEQ];
#pragma unroll
            for (int s = 0; s < NSEQ; s++) {
                af[s] = __shfl_down_sync(0xFFFFFFFFu, av[s], 8);
                ag[s] = __shfl_down_sync(0xFFFFFFFFu, av[s], 16);
                ao[s] = __shfl_down_sync(0xFFFFFFFFu, av[s], 24);
            }
            if (g == 0 && active) {
                if (j < HID) {
#pragma unroll
                    for (int s = 0; s < NSEQ; s++) {
                        cst[s] = fmaf(af[s], cst[s], av[s] * ag[s]);
                        hbuf[1 - rd][s][j] = ao[s] * tanh_u(cst[s]);
                    }
                } else if ((t0 | dt) != 0) {   // layer-2 cell, skip spurious t=0
#pragma unroll
                    for (int s = 0; s < NSEQ; s++) {
                        cst[s] = fmaf(af[s], cst[s], av[s] * ag[s]);
                        float y = ao[s] * tanh_u(cst[s]);
                        ob_sh[s][dt] = y;
                        h2b[s] = y;
                    }
                }
            }
            if (wid == 7) {                    // broadcast h2 to all warp-7 lanes
#pragma unroll
                for (int s = 0; s < NSEQ; s++)
                    h2b[s] = __shfl_sync(0xFFFFFFFFu, h2b[s], 2);
            }
            __syncthreads();
        }
        // ---- flush outputs (lagged by 1) + stage next chunk ------------
        {
            int s = tid >> 6, col = tid & 63;
            int t = t0 - 1 + col;
            if (t >= 0) out[(n0 + s) * TT + t] = ob_sh[s][col];
        }
        if (t0 + CHUNK < TT && tid < 64) {
            int s = tid >> 4, q = (tid & 15) * 4;
            float4 v = *(const float4*)&stim[(n0 + s) * TT + t0 + CHUNK + q];
            x_sh[q + 0][s] = v.x; x_sh[q + 1][s] = v.y;
            x_sh[q + 2][s] = v.z; x_sh[q + 3][s] = v.w;
        }
        __syncthreads();
    }

    // ---- tail: y(2047) from h1(2047) (in hbuf[0]) ----------------------
    if (wid == 7) {
        u64 acc[NSEQ];
#pragma unroll
        for (int s = 0; s < NSEQ; s++)
            acc[s] = pack2(fmaf(wi, h2b[s], bias), 0.f);
#pragma unroll
        for (int kk = 0; kk < KP / 2; kk++) {
#pragma unroll
            for (int s = 0; s < NSEQ; s++) {
                ulonglong2 hv = ((const ulonglong2*)&hbuf[0][s][0])[kk];
                acc[s] = fma2(wreg[2*kk],   hv.x, acc[s]);
                acc[s] = fma2(wreg[2*kk+1], hv.y, acc[s]);
            }
        }
        float av[NSEQ];
#pragma unroll
        for (int s = 0; s < NSEQ; s++) {
            float lo, hi; unpack2(acc[s], lo, hi);
            float gt = lo + hi;
            av[s] = fmaf(aB, rcpf(ex2f(gt * aC) + 1.0f), aA);
        }
#pragma unroll
        for (int s = 0; s < NSEQ; s++) {
            float af = __shfl_down_sync(0xFFFFFFFFu, av[s], 8);
            float ag = __shfl_down_sync(0xFFFFFFFFu, av[s], 16);
            float ao = __shfl_down_sync(0xFFFFFFFFu, av[s], 24);
            if (g == 0 && isl2) {
                cst[s] = fmaf(af, cst[s], av[s] * ag);
                out[(n0 + s) * TT + (TT - 1)] = ao * tanh_u(cst[s]);
            }
        }
    }
}

extern "C" void kernel_launch(void* const* d_in, const int* in_sizes, int n_in,
                              void* d_out, int out_size)
{
    (void)in_sizes; (void)n_in; (void)out_size;
    const float* stim  = (const float*)d_in[0];
    const float* Wih1  = (const float*)d_in[1];
    const float* Whh1  = (const float*)d_in[2];
    const float* bih1  = (const float*)d_in[3];
    const float* bhh1  = (const float*)d_in[4];
    const float* Wih2  = (const float*)d_in[5];
    const float* Whh2  = (const float*)d_in[6];
    const float* bih2  = (const float*)d_in[7];
    const float* bhh2  = (const float*)d_in[8];
    float* out = (float*)d_out;

    lstm2_kernel<<<NN / NSEQ, NTHREADS>>>(stim, Wih1, Whh1, bih1, bhh1,
                                          Wih2, Whh2, bih2, bhh2, out);
}

// round 4
// speedup vs baseline: 1.8643x; 1.1019x over previous
#include <cuda_runtime.h>

#define HID   51
#define NSEQ  4
#define TT    2048
#define NN    1024
#define CHUNK 64
#define HPAD  52         // h row stride (floats); [51] is a permanent zero pad
#define NTHREADS 224     // 7 warps; tid = j*4+g, j=0..50 layer-1, j=51 layer-2

typedef unsigned long long u64;

__device__ __forceinline__ u64 pack2(float lo, float hi) {
    u64 r; asm("mov.b64 %0, {%1,%2};" : "=l"(r) : "f"(lo), "f"(hi)); return r;
}
__device__ __forceinline__ void unpack2(u64 v, float& lo, float& hi) {
    asm("mov.b64 {%0,%1}, %2;" : "=f"(lo), "=f"(hi) : "l"(v));
}
__device__ __forceinline__ u64 fma2(u64 a, u64 b, u64 c) {
    u64 d; asm("fma.rn.f32x2 %0, %1, %2, %3;" : "=l"(d) : "l"(a), "l"(b), "l"(c));
    return d;
}
__device__ __forceinline__ u64 add2(u64 a, u64 b) {
    u64 d; asm("add.rn.f32x2 %0, %1, %2;" : "=l"(d) : "l"(a), "l"(b));
    return d;
}
__device__ __forceinline__ float tanhx(float x) {
    float r; asm("tanh.approx.f32 %0, %1;" : "=f"(r) : "f"(x)); return r;
}

__global__ void __launch_bounds__(NTHREADS, 2)
lstm2_kernel(const float* __restrict__ stim,
             const float* __restrict__ Wih1,   // (204,1)
             const float* __restrict__ Whh1,   // (204,51)
             const float* __restrict__ bih1,
             const float* __restrict__ bhh1,
             const float* __restrict__ Wih2,   // (4,51)
             const float* __restrict__ Whh2,   // (4,1)
             const float* __restrict__ bih2,
             const float* __restrict__ bhh2,
             float* __restrict__ out)          // (1024,2048)
{
    __shared__ __align__(16) float hbuf[2][NSEQ][HPAD];
    __shared__ __align__(16) float x_sh[CHUNK][NSEQ];   // [dt][s]
    __shared__ __align__(16) float ob_sh[NSEQ][CHUNK];  // [s][dt] = y(t0+dt-1)

    const int tid  = threadIdx.x;
    const int wid  = tid >> 5;
    const int lane = tid & 31;
    const int j    = tid >> 2;         // hidden index; 51 => layer-2 rows
    const int g    = tid & 3;          // gate 0..3 (i,f,g,o)
    const int n0   = blockIdx.x * NSEQ;
    const bool isl1 = (j < HID);
    const bool isl2 = (j == HID);      // tid 204..207 (warp 6 lanes 12..15)
    const bool g0   = (g == 0);

    // ---- per-lane weights in registers ---------------------------------
    u64 wreg[26];
#pragma unroll
    for (int kk = 0; kk < 26; kk++) wreg[kk] = 0ull;
    float bias = 0.f, wi = 0.f;
    if (isl1 || isl2) {
        const float* wr = isl2 ? (Wih2 + g * HID)
                               : (Whh1 + (g * HID + j) * HID);
#pragma unroll
        for (int kk = 0; kk < 26; kk++) {
            float a = wr[2*kk];
            float b = (2*kk + 1 < HID) ? wr[2*kk + 1] : 0.f;
            wreg[kk] = pack2(a, b);
        }
        if (isl2) { bias = bih2[g] + bhh2[g]; wi = Whh2[g]; }
        else      { bias = bih1[g*HID + j] + bhh1[g*HID + j]; wi = Wih1[g*HID + j]; }
    }
    // unified activation: act = aB * tanh(aC * x) + aA
    const float aC = (g == 2) ? 1.0f : 0.5f;
    const float aB = (g == 2) ? 1.0f : 0.5f;
    const float aA = (g == 2) ? 0.0f : 0.5f;

    for (int i = tid; i < 2 * NSEQ * HPAD; i += NTHREADS)
        ((float*)hbuf)[i] = 0.f;

    float cst[NSEQ];                   // c1 (j<51 g0 lanes) / c2 (j==51 g0 lane)
#pragma unroll
    for (int s = 0; s < NSEQ; s++) cst[s] = 0.f;
    float h2b[NSEQ];
#pragma unroll
    for (int s = 0; s < NSEQ; s++) h2b[s] = 0.f;

    // stage chunk 0 stimulus (transposed)
    if (tid < 64) {
        int s = tid >> 4, q = (tid & 15) * 4;
        float4 v = *(const float4*)&stim[(n0 + s) * TT + q];
        x_sh[q + 0][s] = v.x; x_sh[q + 1][s] = v.y;
        x_sh[q + 2][s] = v.z; x_sh[q + 3][s] = v.w;
    }
    __syncthreads();

#pragma unroll 1
    for (int t0 = 0; t0 < TT; t0 += CHUNK) {
#pragma unroll 2
        for (int dt = 0; dt < CHUNK; dt++) {
            const int rd = dt & 1;
            // ---- matvec: split chains, FMA2 ----------------------------
            float4 xv = *(const float4*)&x_sh[dt][0];
            float xin[NSEQ] = {xv.x, xv.y, xv.z, xv.w};
            if (isl2) {
#pragma unroll
                for (int s = 0; s < NSEQ; s++) xin[s] = h2b[s];
            }
            u64 accA[NSEQ], accB[NSEQ];
#pragma unroll
            for (int s = 0; s < NSEQ; s++) {
                accA[s] = pack2(fmaf(wi, xin[s], bias), 0.f);
                accB[s] = 0ull;
            }
#pragma unroll
            for (int kk = 0; kk < 13; kk++) {
#pragma unroll
                for (int s = 0; s < NSEQ; s++) {
                    ulonglong2 hv = ((const ulonglong2*)&hbuf[rd][s][0])[kk];
                    accA[s] = fma2(wreg[2*kk],   hv.x, accA[s]);
                    accB[s] = fma2(wreg[2*kk+1], hv.y, accB[s]);
                }
            }
            // ---- activation --------------------------------------------
            float av[NSEQ];
#pragma unroll
            for (int s = 0; s < NSEQ; s++) {
                float lo, hi; unpack2(add2(accA[s], accB[s]), lo, hi);
                float gt = lo + hi;
                av[s] = fmaf(aB, tanhx(gt * aC), aA);
            }
            // ---- gate exchange (nibble) + cell update ------------------
            float af[NSEQ], ag[NSEQ], ao[NSEQ];
#pragma unroll
            for (int s = 0; s < NSEQ; s++) {
                af[s] = __shfl_down_sync(0xFFFFFFFFu, av[s], 1);
                ag[s] = __shfl_down_sync(0xFFFFFFFFu, av[s], 2);
                ao[s] = __shfl_down_sync(0xFFFFFFFFu, av[s], 3);
            }
            if (g0) {
                if (isl1) {
#pragma unroll
                    for (int s = 0; s < NSEQ; s++) {
                        cst[s] = fmaf(af[s], cst[s], av[s] * ag[s]);
                        hbuf[1 - rd][s][j] = ao[s] * tanhx(cst[s]);
                    }
                } else if (isl2 && (t0 | dt) != 0) {
#pragma unroll
                    for (int s = 0; s < NSEQ; s++) {
                        cst[s] = fmaf(af[s], cst[s], av[s] * ag[s]);
                        float y = ao[s] * tanhx(cst[s]);
                        ob_sh[s][dt] = y;
                        h2b[s] = y;
                    }
                }
            }
            if (wid == 6) {
#pragma unroll
                for (int s = 0; s < NSEQ; s++)
                    h2b[s] = __shfl_sync(0xFFFFFFFFu, h2b[s], 12);
            }
            __syncthreads();
        }
        // ---- flush outputs (lagged by 1) + stage next chunk ------------
        for (int i = tid; i < NSEQ * CHUNK; i += NTHREADS) {
            int s = i >> 6, col = i & 63;
            int t = t0 - 1 + col;
            if (t >= 0) out[(n0 + s) * TT + t] = ob_sh[s][col];
        }
        if (t0 + CHUNK < TT && tid < 64) {
            int s = tid >> 4, q = (tid & 15) * 4;
            float4 v = *(const float4*)&stim[(n0 + s) * TT + t0 + CHUNK + q];
            x_sh[q + 0][s] = v.x; x_sh[q + 1][s] = v.y;
            x_sh[q + 2][s] = v.z; x_sh[q + 3][s] = v.w;
        }
        __syncthreads();
    }

    // ---- tail: y(2047) from h1(2047) (in hbuf[0]) ----------------------
    if (wid == 6) {
        u64 accA[NSEQ], accB[NSEQ];
#pragma unroll
        for (int s = 0; s < NSEQ; s++) {
            accA[s] = pack2(fmaf(wi, h2b[s], bias), 0.f);
            accB[s] = 0ull;
        }
#pragma unroll
        for (int kk = 0; kk < 13; kk++) {
#pragma unroll
            for (int s = 0; s < NSEQ; s++) {
                ulonglong2 hv = ((const ulonglong2*)&hbuf[0][s][0])[kk];
                accA[s] = fma2(wreg[2*kk],   hv.x, accA[s]);
                accB[s] = fma2(wreg[2*kk+1], hv.y, accB[s]);
            }
        }
        float av[NSEQ];
#pragma unroll
        for (int s = 0; s < NSEQ; s++) {
            float lo, hi; unpack2(add2(accA[s], accB[s]), lo, hi);
            float gt = lo + hi;
            av[s] = fmaf(aB, tanhx(gt * aC), aA);
        }
#pragma unroll
        for (int s = 0; s < NSEQ; s++) {
            float af = __shfl_down_sync(0xFFFFFFFFu, av[s], 1);
            float ag = __shfl_down_sync(0xFFFFFFFFu, av[s], 2);
            float ao = __shfl_down_sync(0xFFFFFFFFu, av[s], 3);
            if (g0 && isl2) {
                cst[s] = fmaf(af, cst[s], av[s] * ag);
                out[(n0 + s) * TT + (TT - 1)] = ao * tanhx(cst[s]);
            }
        }
    }
}

extern "C" void kernel_launch(void* const* d_in, const int* in_sizes, int n_in,
                              void* d_out, int out_size)
{
    (void)in_sizes; (void)n_in; (void)out_size;
    const float* stim  = (const float*)d_in[0];
    const float* Wih1  = (const float*)d_in[1];
    const float* Whh1  = (const float*)d_in[2];
    const float* bih1  = (const float*)d_in[3];
    const float* bhh1  = (const float*)d_in[4];
    const float* Wih2  = (const float*)d_in[5];
    const float* Whh2  = (const float*)d_in[6];
    const float* bih2  = (const float*)d_in[7];
    const float* bhh2  = (const float*)d_in[8];
    float* out = (float*)d_out;

    lstm2_kernel<<<NN / NSEQ, NTHREADS>>>(stim, Wih1, Whh1, bih1, bhh1,
                                          Wih2, Whh2, bih2, bhh2, out);
}

// round 5
// speedup vs baseline: 1.9912x; 1.0680x over previous
#include <cuda_runtime.h>

#define HID   51
#define NSEQ  2
#define TT    2048
#define NN    1024
#define CHUNK 64
#define HPAD  52          // h row stride (floats); [51] permanent zero pad
#define NTHREADS 128      // 4 warps; tid = jA*4+g; row B = jA+32 (jA<20)

typedef unsigned long long u64;

__device__ __forceinline__ u64 pack2(float lo, float hi) {
    u64 r; asm("mov.b64 %0, {%1,%2};" : "=l"(r) : "f"(lo), "f"(hi)); return r;
}
__device__ __forceinline__ void unpack2(u64 v, float& lo, float& hi) {
    asm("mov.b64 {%0,%1}, %2;" : "=f"(lo), "=f"(hi) : "l"(v));
}
__device__ __forceinline__ u64 fma2(u64 a, u64 b, u64 c) {
    u64 d; asm("fma.rn.f32x2 %0, %1, %2, %3;" : "=l"(d) : "l"(a), "l"(b), "l"(c));
    return d;
}
__device__ __forceinline__ float tanhx(float x) {
    float r; asm("tanh.approx.f32 %0, %1;" : "=f"(r) : "f"(x)); return r;
}

__global__ void __launch_bounds__(NTHREADS, 4)
lstm2_kernel(const float* __restrict__ stim,
             const float* __restrict__ Wih1,   // (204,1)
             const float* __restrict__ Whh1,   // (204,51)
             const float* __restrict__ bih1,
             const float* __restrict__ bhh1,
             const float* __restrict__ Wih2,   // (4,51)
             const float* __restrict__ Whh2,   // (4,1)
             const float* __restrict__ bih2,
             const float* __restrict__ bhh2,
             float* __restrict__ out)          // (1024,2048)
{
    __shared__ __align__(16) float hbuf[2][NSEQ][HPAD];
    __shared__ __align__(8)  float x_sh[CHUNK][NSEQ];   // [dt][s]
    __shared__ __align__(16) float ob_sh[NSEQ][CHUNK];  // [s][dt] = y(t0+dt-1)

    const int tid  = threadIdx.x;
    const int wid  = tid >> 5;
    const int g    = tid & 3;          // gate 0..3 (i,f,g,o)
    const int jA   = tid >> 2;         // row A hidden index 0..31
    const int jB   = jA + 32;          // row B hidden index; 51 => layer-2
    const int n0   = blockIdx.x * NSEQ;
    const bool bRow = (jA < 20);       // B row exists (jB <= 51)
    const bool isl2 = (jA == 19);      // layer-2 gate rows (tid 76..79, warp 2)
    const bool g0   = (g == 0);

    // ---- per-lane weights in registers (two rows) -----------------------
    u64 wA[26], wB[26];
    float biasA, wiA, biasB = 0.f, wiB = 0.f;
    {
        const int rowA = g * HID + jA;
        const float* wr = Whh1 + rowA * HID;
#pragma unroll
        for (int kk = 0; kk < 26; kk++) {
            float a = wr[2*kk];
            float b = (2*kk + 1 < HID) ? wr[2*kk + 1] : 0.f;
            wA[kk] = pack2(a, b);
        }
        biasA = bih1[rowA] + bhh1[rowA];
        wiA   = Wih1[rowA];
    }
#pragma unroll
    for (int kk = 0; kk < 26; kk++) wB[kk] = 0ull;
    if (bRow) {
        const float* wr;
        if (isl2) { wr = Wih2 + g * HID; biasB = bih2[g] + bhh2[g]; wiB = Whh2[g]; }
        else {
            const int rowB = g * HID + jB;
            wr = Whh1 + rowB * HID;
            biasB = bih1[rowB] + bhh1[rowB];
            wiB   = Wih1[rowB];
        }
#pragma unroll
        for (int kk = 0; kk < 26; kk++) {
            float a = wr[2*kk];
            float b = (2*kk + 1 < HID) ? wr[2*kk + 1] : 0.f;
            wB[kk] = pack2(a, b);
        }
    }
    // unified activation: act = aB * tanh(aC * x) + aA  (sigmoid unless g==2)
    const float aC = (g == 2) ? 1.0f : 0.5f;
    const float aB = (g == 2) ? 1.0f : 0.5f;
    const float aA = (g == 2) ? 0.0f : 0.5f;

    for (int i = tid; i < 2 * NSEQ * HPAD; i += NTHREADS)
        ((float*)hbuf)[i] = 0.f;

    float cstA[NSEQ] = {0.f, 0.f};
    float cstB[NSEQ] = {0.f, 0.f};
    float h2b[NSEQ]  = {0.f, 0.f};

    // stage chunk 0 stimulus (transposed)
    if (tid < 32) {
        int s = tid >> 4, q = (tid & 15) * 4;
        float4 v = *(const float4*)&stim[(n0 + s) * TT + q];
        x_sh[q + 0][s] = v.x; x_sh[q + 1][s] = v.y;
        x_sh[q + 2][s] = v.z; x_sh[q + 3][s] = v.w;
    }
    __syncthreads();

#pragma unroll 1
    for (int t0 = 0; t0 < TT; t0 += CHUNK) {
#pragma unroll 2
        for (int dt = 0; dt < CHUNK; dt++) {
            const int rd = dt & 1;
            float2 xv = *(const float2*)&x_sh[dt][0];
            float xB0 = isl2 ? h2b[0] : xv.x;
            float xB1 = isl2 ? h2b[1] : xv.y;

            u64 aA0 = pack2(fmaf(wiA, xv.x, biasA), 0.f);
            u64 aA1 = pack2(fmaf(wiA, xv.y, biasA), 0.f);
            u64 aB0 = pack2(fmaf(wiB, xB0, biasB), 0.f);
            u64 aB1 = pack2(fmaf(wiB, xB1, biasB), 0.f);
#pragma unroll
            for (int kk = 0; kk < 13; kk++) {
                ulonglong2 hv0 = ((const ulonglong2*)&hbuf[rd][0][0])[kk];
                ulonglong2 hv1 = ((const ulonglong2*)&hbuf[rd][1][0])[kk];
                aA0 = fma2(wA[2*kk],   hv0.x, aA0);
                aA0 = fma2(wA[2*kk+1], hv0.y, aA0);
                aA1 = fma2(wA[2*kk],   hv1.x, aA1);
                aA1 = fma2(wA[2*kk+1], hv1.y, aA1);
                aB0 = fma2(wB[2*kk],   hv0.x, aB0);
                aB0 = fma2(wB[2*kk+1], hv0.y, aB0);
                aB1 = fma2(wB[2*kk],   hv1.x, aB1);
                aB1 = fma2(wB[2*kk+1], hv1.y, aB1);
            }
            // ---- activations -------------------------------------------
            float avA[NSEQ], avB[NSEQ];
            {
                float lo, hi;
                unpack2(aA0, lo, hi); avA[0] = fmaf(aB, tanhx((lo + hi) * aC), aA);
                unpack2(aA1, lo, hi); avA[1] = fmaf(aB, tanhx((lo + hi) * aC), aA);
                unpack2(aB0, lo, hi); avB[0] = fmaf(aB, tanhx((lo + hi) * aC), aA);
                unpack2(aB1, lo, hi); avB[1] = fmaf(aB, tanhx((lo + hi) * aC), aA);
            }
            // ---- gate exchange (nibble, dist 1/2/3) + cell update ------
            float afA[NSEQ], agA[NSEQ], aoA[NSEQ];
            float afB[NSEQ], agB[NSEQ], aoB[NSEQ];
#pragma unroll
            for (int s = 0; s < NSEQ; s++) {
                afA[s] = __shfl_down_sync(0xFFFFFFFFu, avA[s], 1);
                agA[s] = __shfl_down_sync(0xFFFFFFFFu, avA[s], 2);
                aoA[s] = __shfl_down_sync(0xFFFFFFFFu, avA[s], 3);
                afB[s] = __shfl_down_sync(0xFFFFFFFFu, avB[s], 1);
                agB[s] = __shfl_down_sync(0xFFFFFFFFu, avB[s], 2);
                aoB[s] = __shfl_down_sync(0xFFFFFFFFu, avB[s], 3);
            }
            if (g0) {
#pragma unroll
                for (int s = 0; s < NSEQ; s++) {
                    cstA[s] = fmaf(afA[s], cstA[s], avA[s] * agA[s]);
                    hbuf[1 - rd][s][jA] = aoA[s] * tanhx(cstA[s]);
                }
                if (bRow) {
                    if (!isl2) {
#pragma unroll
                        for (int s = 0; s < NSEQ; s++) {
                            cstB[s] = fmaf(afB[s], cstB[s], avB[s] * agB[s]);
                            hbuf[1 - rd][s][jB] = aoB[s] * tanhx(cstB[s]);
                        }
                    } else if ((t0 | dt) != 0) {
#pragma unroll
                        for (int s = 0; s < NSEQ; s++) {
                            cstB[s] = fmaf(afB[s], cstB[s], avB[s] * agB[s]);
                            float y = aoB[s] * tanhx(cstB[s]);
                            ob_sh[s][dt] = y;
                            h2b[s] = y;
                        }
                    }
                }
            }
            if (wid == 2) {                    // broadcast h2 within warp 2
#pragma unroll
                for (int s = 0; s < NSEQ; s++)
                    h2b[s] = __shfl_sync(0xFFFFFFFFu, h2b[s], 12);
            }
            __syncthreads();
        }
        // ---- flush outputs (lagged by 1) + stage next chunk ------------
        {
            int s = tid >> 6, col = tid & 63;
            int t = t0 - 1 + col;
            if (t >= 0) out[(n0 + s) * TT + t] = ob_sh[s][col];
        }
        if (t0 + CHUNK < TT && tid < 32) {
            int s = tid >> 4, q = (tid & 15) * 4;
            float4 v = *(const float4*)&stim[(n0 + s) * TT + t0 + CHUNK + q];
            x_sh[q + 0][s] = v.x; x_sh[q + 1][s] = v.y;
            x_sh[q + 2][s] = v.z; x_sh[q + 3][s] = v.w;
        }
        __syncthreads();
    }

    // ---- tail: y(2047) from h1(2047) (in hbuf[0]) ----------------------
    if (wid == 2) {
        u64 aB0 = pack2(fmaf(wiB, h2b[0], biasB), 0.f);
        u64 aB1 = pack2(fmaf(wiB, h2b[1], biasB), 0.f);
#pragma unroll
        for (int kk = 0; kk < 13; kk++) {
            ulonglong2 hv0 = ((const ulonglong2*)&hbuf[0][0][0])[kk];
            ulonglong2 hv1 = ((const ulonglong2*)&hbuf[0][1][0])[kk];
            aB0 = fma2(wB[2*kk],   hv0.x, aB0);
            aB0 = fma2(wB[2*kk+1], hv0.y, aB0);
            aB1 = fma2(wB[2*kk],   hv1.x, aB1);
            aB1 = fma2(wB[2*kk+1], hv1.y, aB1);
        }
        float avB[NSEQ];
        float lo, hi;
        unpack2(aB0, lo, hi); avB[0] = fmaf(aB, tanhx((lo + hi) * aC), aA);
        unpack2(aB1, lo, hi); avB[1] = fmaf(aB, tanhx((lo + hi) * aC), aA);
#pragma unroll
        for (int s = 0; s < NSEQ; s++) {
            float af = __shfl_down_sync(0xFFFFFFFFu, avB[s], 1);
            float ag = __shfl_down_sync(0xFFFFFFFFu, avB[s], 2);
            float ao = __shfl_down_sync(0xFFFFFFFFu, avB[s], 3);
            if (g0 && isl2) {
                cstB[s] = fmaf(af, cstB[s], avB[s] * ag);
                out[(n0 + s) * TT + (TT - 1)] = ao * tanhx(cstB[s]);
            }
        }
    }
}

extern "C" void kernel_launch(void* const* d_in, const int* in_sizes, int n_in,
                              void* d_out, int out_size)
{
    (void)in_sizes; (void)n_in; (void)out_size;
    const float* stim  = (const float*)d_in[0];
    const float* Wih1  = (const float*)d_in[1];
    const float* Whh1  = (const float*)d_in[2];
    const float* bih1  = (const float*)d_in[3];
    const float* bhh1  = (const float*)d_in[4];
    const float* Wih2  = (const float*)d_in[5];
    const float* Whh2  = (const float*)d_in[6];
    const float* bih2  = (const float*)d_in[7];
    const float* bhh2  = (const float*)d_in[8];
    float* out = (float*)d_out;

    lstm2_kernel<<<NN / NSEQ, NTHREADS>>>(stim, Wih1, Whh1, bih1, bhh1,
                                          Wih2, Whh2, bih2, bhh2, out);
}

// round 6
// speedup vs baseline: 2.0165x; 1.0127x over previous
#include <cuda_runtime.h>

#define HID   51
#define NSEQ  2
#define TT    2048
#define NN    1024
#define CHUNK 64
#define HPAD  52          // h row stride (floats); [51] permanent zero pad
#define NTHREADS 224      // 7 warps; tid = j*4+g, j=0..51 (j==51 -> layer 2)

typedef unsigned long long u64;

__device__ __forceinline__ u64 pack2(float lo, float hi) {
    u64 r; asm("mov.b64 %0, {%1,%2};" : "=l"(r) : "f"(lo), "f"(hi)); return r;
}
__device__ __forceinline__ void unpack2(u64 v, float& lo, float& hi) {
    asm("mov.b64 {%0,%1}, %2;" : "=f"(lo), "=f"(hi) : "l"(v));
}
__device__ __forceinline__ u64 fma2(u64 a, u64 b, u64 c) {
    u64 d; asm("fma.rn.f32x2 %0, %1, %2, %3;" : "=l"(d) : "l"(a), "l"(b), "l"(c));
    return d;
}
__device__ __forceinline__ float tanhx(float x) {
    float r; asm("tanh.approx.f32 %0, %1;" : "=f"(r) : "f"(x)); return r;
}

__global__ void __launch_bounds__(NTHREADS, 4)
lstm2_kernel(const float* __restrict__ stim,
             const float* __restrict__ Wih1,   // (204,1)
             const float* __restrict__ Whh1,   // (204,51)
             const float* __restrict__ bih1,
             const float* __restrict__ bhh1,
             const float* __restrict__ Wih2,   // (4,51)
             const float* __restrict__ Whh2,   // (4,1)
             const float* __restrict__ bih2,
             const float* __restrict__ bhh2,
             float* __restrict__ out)          // (1024,2048)
{
    __shared__ __align__(16) float hbuf[2][NSEQ][HPAD];
    __shared__ __align__(8)  float x_sh[CHUNK][NSEQ];   // [dt][s]
    __shared__ __align__(16) float ob_sh[NSEQ][CHUNK];  // [s][dt] = y(t0+dt-1)
    __shared__ float h2_sh[NSEQ];                       // h2 state (layer-2)

    const int tid  = threadIdx.x;
    const int wid  = tid >> 5;
    const int j    = tid >> 2;         // hidden index; 51 => layer-2 rows
    const int g    = tid & 3;          // gate 0..3 (i,f,g,o)
    const int n0   = blockIdx.x * NSEQ;
    const bool isl1 = (j < HID);
    const bool isl2 = (j == HID);      // tid 204..207 (warp 6, lanes 12..15)
    const bool g0   = (g == 0);
    const bool gg2  = (g == 2);        // tanh gate

    // ---- per-lane weights in registers (one row) ------------------------
    u64 wreg[26];
#pragma unroll
    for (int kk = 0; kk < 26; kk++) wreg[kk] = 0ull;
    float bias = 0.f, wi = 0.f;
    if (isl1 || isl2) {
        const float* wr = isl2 ? (Wih2 + g * HID)
                               : (Whh1 + (g * HID + j) * HID);
#pragma unroll
        for (int kk = 0; kk < 26; kk++) {
            float a = wr[2*kk];
            float b = (2*kk + 1 < HID) ? wr[2*kk + 1] : 0.f;
            wreg[kk] = pack2(a, b);
        }
        if (isl2) { bias = bih2[g] + bhh2[g]; wi = Whh2[g]; }
        else      { bias = bih1[g*HID + j] + bhh1[g*HID + j]; wi = Wih1[g*HID + j]; }
    }

    for (int i = tid; i < 2 * NSEQ * HPAD; i += NTHREADS)
        ((float*)hbuf)[i] = 0.f;
    if (tid < NSEQ) h2_sh[tid] = 0.f;

    float cst[NSEQ] = {0.f, 0.f};      // c1 (g0, j<51) / c2 (g0, j==51)

    // stage chunk 0 stimulus (transposed)
    if (tid < 32) {
        int s = tid >> 4, q = (tid & 15) * 4;
        float4 v = *(const float4*)&stim[(n0 + s) * TT + q];
        x_sh[q + 0][s] = v.x; x_sh[q + 1][s] = v.y;
        x_sh[q + 2][s] = v.z; x_sh[q + 3][s] = v.w;
    }
    __syncthreads();

#pragma unroll 1
    for (int t0 = 0; t0 < TT; t0 += CHUNK) {
#pragma unroll 2
        for (int dt = 0; dt < CHUNK; dt++) {
            const int rd = dt & 1;
            // ---- matvec: one row, two seqs, FMA2 -----------------------
            float2 xv = *(const float2*)&x_sh[dt][0];
            float x0 = xv.x, x1 = xv.y;
            if (isl2) { x0 = h2_sh[0]; x1 = h2_sh[1]; }

            u64 a0 = pack2(fmaf(wi, x0, bias), 0.f);
            u64 a1 = pack2(fmaf(wi, x1, bias), 0.f);
#pragma unroll
            for (int kk = 0; kk < 13; kk++) {
                ulonglong2 hv0 = ((const ulonglong2*)&hbuf[rd][0][0])[kk];
                ulonglong2 hv1 = ((const ulonglong2*)&hbuf[rd][1][0])[kk];
                a0 = fma2(wreg[2*kk],   hv0.x, a0);
                a0 = fma2(wreg[2*kk+1], hv0.y, a0);
                a1 = fma2(wreg[2*kk],   hv1.x, a1);
                a1 = fma2(wreg[2*kk+1], hv1.y, a1);
            }
            // ---- activation (selp-immediate constants) -----------------
            float av[NSEQ];
            {
                float lo, hi;
                unpack2(a0, lo, hi);
                float gt = lo + hi;
                float th = tanhx(gg2 ? gt : 0.5f * gt);
                av[0] = gg2 ? th : fmaf(0.5f, th, 0.5f);
                unpack2(a1, lo, hi);
                gt = lo + hi;
                th = tanhx(gg2 ? gt : 0.5f * gt);
                av[1] = gg2 ? th : fmaf(0.5f, th, 0.5f);
            }
            // ---- gate exchange (nibble, dist 1/2/3) + cell update ------
            float af[NSEQ], ag[NSEQ], ao[NSEQ];
#pragma unroll
            for (int s = 0; s < NSEQ; s++) {
                af[s] = __shfl_down_sync(0xFFFFFFFFu, av[s], 1);
                ag[s] = __shfl_down_sync(0xFFFFFFFFu, av[s], 2);
                ao[s] = __shfl_down_sync(0xFFFFFFFFu, av[s], 3);
            }
            if (g0) {
                if (isl1) {
#pragma unroll
                    for (int s = 0; s < NSEQ; s++) {
                        cst[s] = fmaf(af[s], cst[s], av[s] * ag[s]);
                        hbuf[1 - rd][s][j] = ao[s] * tanhx(cst[s]);
                    }
                } else if (isl2 && (t0 | dt) != 0) {
#pragma unroll
                    for (int s = 0; s < NSEQ; s++) {
                        cst[s] = fmaf(af[s], cst[s], av[s] * ag[s]);
                        float y = ao[s] * tanhx(cst[s]);
                        ob_sh[s][dt] = y;
                        h2_sh[s] = y;
                    }
                }
            }
            __syncthreads();
        }
        // ---- flush outputs (lagged by 1) + stage next chunk ------------
        if (tid < 128) {
            int s = tid >> 6, col = tid & 63;
            int t = t0 - 1 + col;
            if (t >= 0) out[(n0 + s) * TT + t] = ob_sh[s][col];
        }
        if (t0 + CHUNK < TT && tid < 32) {
            int s = tid >> 4, q = (tid & 15) * 4;
            float4 v = *(const float4*)&stim[(n0 + s) * TT + t0 + CHUNK + q];
            x_sh[q + 0][s] = v.x; x_sh[q + 1][s] = v.y;
            x_sh[q + 2][s] = v.z; x_sh[q + 3][s] = v.w;
        }
        __syncthreads();
    }

    // ---- tail: y(2047) from h1(2047) (in hbuf[0]) ----------------------
    if (wid == 6) {
        float x0 = h2_sh[0], x1 = h2_sh[1];
        u64 a0 = pack2(fmaf(wi, x0, bias), 0.f);
        u64 a1 = pack2(fmaf(wi, x1, bias), 0.f);
#pragma unroll
        for (int kk = 0; kk < 13; kk++) {
            ulonglong2 hv0 = ((const ulonglong2*)&hbuf[0][0][0])[kk];
            ulonglong2 hv1 = ((const ulonglong2*)&hbuf[0][1][0])[kk];
            a0 = fma2(wreg[2*kk],   hv0.x, a0);
            a0 = fma2(wreg[2*kk+1], hv0.y, a0);
            a1 = fma2(wreg[2*kk],   hv1.x, a1);
            a1 = fma2(wreg[2*kk+1], hv1.y, a1);
        }
        float av[NSEQ];
        float lo, hi;
        unpack2(a0, lo, hi);
        float gt = lo + hi;
        float th = tanhx(gg2 ? gt : 0.5f * gt);
        av[0] = gg2 ? th : fmaf(0.5f, th, 0.5f);
        unpack2(a1, lo, hi);
        gt = lo + hi;
        th = tanhx(gg2 ? gt : 0.5f * gt);
        av[1] = gg2 ? th : fmaf(0.5f, th, 0.5f);
#pragma unroll
        for (int s = 0; s < NSEQ; s++) {
            float af = __shfl_down_sync(0xFFFFFFFFu, av[s], 1);
            float ag = __shfl_down_sync(0xFFFFFFFFu, av[s], 2);
            float ao = __shfl_down_sync(0xFFFFFFFFu, av[s], 3);
            if (g0 && isl2) {
                cst[s] = fmaf(af, cst[s], av[s] * ag);
                out[(n0 + s) * TT + (TT - 1)] = ao * tanhx(cst[s]);
            }
        }
    }
}

extern "C" void kernel_launch(void* const* d_in, const int* in_sizes, int n_in,
                              void* d_out, int out_size)
{
    (void)in_sizes; (void)n_in; (void)out_size;
    const float* stim  = (const float*)d_in[0];
    const float* Wih1  = (const float*)d_in[1];
    const float* Whh1  = (const float*)d_in[2];
    const float* bih1  = (const float*)d_in[3];
    const float* bhh1  = (const float*)d_in[4];
    const float* Wih2  = (const float*)d_in[5];
    const float* Whh2  = (const float*)d_in[6];
    const float* bih2  = (const float*)d_in[7];
    const float* bhh2  = (const float*)d_in[8];
    float* out = (float*)d_out;

    lstm2_kernel<<<NN / NSEQ, NTHREADS>>>(stim, Wih1, Whh1, bih1, bhh1,
                                          Wih2, Whh2, bih2, bhh2, out);
}

// round 7
// speedup vs baseline: 2.5965x; 1.2876x over previous
#include <cuda_runtime.h>
#include <cuda_fp16.h>

#define HID   51
#define NSEQ  2
#define TT    2048
#define NN    1024
#define CHUNK 64
#define H2PAD 28          // half2 per h row (26 used, 2 zero pad) = 7 x uint4
#define NTHREADS 224      // 7 warps; tid = j*4+g, j=0..51 (j==51 -> layer 2)

__device__ __forceinline__ float tanhx(float x) {
    float r; asm("tanh.approx.f32 %0, %1;" : "=f"(r) : "f"(x)); return r;
}

__global__ void __launch_bounds__(NTHREADS, 4)
lstm2_kernel(const float* __restrict__ stim,
             const float* __restrict__ Wih1,   // (204,1)
             const float* __restrict__ Whh1,   // (204,51)
             const float* __restrict__ bih1,
             const float* __restrict__ bhh1,
             const float* __restrict__ Wih2,   // (4,51)
             const float* __restrict__ Whh2,   // (4,1)
             const float* __restrict__ bih2,
             const float* __restrict__ bhh2,
             float* __restrict__ out)          // (1024,2048)
{
    __shared__ __align__(16) __half2 hbuf[2][NSEQ][H2PAD]; // h1 as fp16 pairs
    __shared__ __align__(8)  float x_sh[CHUNK][NSEQ];      // [dt][s]
    __shared__ __align__(16) float ob_sh[NSEQ][CHUNK];     // y(t0+dt-1)
    __shared__ float h2_sh[NSEQ];                          // layer-2 h state

    const int tid  = threadIdx.x;
    const int wid  = tid >> 5;
    const int j    = tid >> 2;         // hidden index; 51 => layer-2 rows
    const int g    = tid & 3;          // gate 0..3 (i,f,g,o)
    const int n0   = blockIdx.x * NSEQ;
    const bool isl1 = (j < HID);
    const bool isl2 = (j == HID);      // tid 204..207 (warp 6, lanes 12..15)
    const bool g0   = (g == 0);
    const bool gg2  = (g == 2);        // tanh gate

    // ---- per-lane weights: fp16x2 k-pairs (26 regs) ---------------------
    __half2 wh[H2PAD];                 // 28 pairs; 26 real + 2 zero
#pragma unroll
    for (int kk = 0; kk < H2PAD; kk++) wh[kk] = __half2half2(__float2half_rn(0.f));
    float bias = 0.f, wi = 0.f;
    if (isl1 || isl2) {
        const float* wr = isl2 ? (Wih2 + g * HID)
                               : (Whh1 + (g * HID + j) * HID);
#pragma unroll
        for (int kk = 0; kk < 26; kk++) {
            float a = wr[2*kk];
            float b = (2*kk + 1 < HID) ? wr[2*kk + 1] : 0.f;
            wh[kk] = __floats2half2_rn(a, b);
        }
        if (isl2) { bias = bih2[g] + bhh2[g]; wi = Whh2[g]; }
        else      { bias = bih1[g*HID + j] + bhh1[g*HID + j]; wi = Wih1[g*HID + j]; }
    }

    for (int i = tid; i < (int)(sizeof(hbuf) / 4); i += NTHREADS)
        ((unsigned*)hbuf)[i] = 0u;     // fp16 zeros (pads stay zero forever)
    if (tid < NSEQ) h2_sh[tid] = 0.f;

    float cst[NSEQ] = {0.f, 0.f};      // c1 (g0, j<51) / c2 (g0, j==51), fp32

    // matvec for one seq: fp16 HFMA2, split chains, fp32 tail
    auto matvec = [&](const __half2* hp, float base) -> float {
        __half2 accA = __half2half2(__float2half_rn(0.f));
        __half2 accB = accA;
        const uint4* hv4 = (const uint4*)hp;
#pragma unroll
        for (int q = 0; q < 7; q++) {          // 7 x LDS.128 = 28 half2
            uint4 v = hv4[q];
            __half2 h0 = *(__half2*)&v.x, h1 = *(__half2*)&v.y;
            __half2 h2 = *(__half2*)&v.z, h3 = *(__half2*)&v.w;
            accA = __hfma2(wh[4*q + 0], h0, accA);
            accB = __hfma2(wh[4*q + 1], h1, accB);
            accA = __hfma2(wh[4*q + 2], h2, accA);
            accB = __hfma2(wh[4*q + 3], h3, accB);
        }
        float2 f = __half22float2(__hadd2(accA, accB));
        return f.x + f.y + base;
    };

    // stage chunk 0 stimulus (transposed)
    if (tid < 32) {
        int s = tid >> 4, q = (tid & 15) * 4;
        float4 v = *(const float4*)&stim[(n0 + s) * TT + q];
        x_sh[q + 0][s] = v.x; x_sh[q + 1][s] = v.y;
        x_sh[q + 2][s] = v.z; x_sh[q + 3][s] = v.w;
    }
    __syncthreads();

#pragma unroll 1
    for (int t0 = 0; t0 < TT; t0 += CHUNK) {
#pragma unroll 2
        for (int dt = 0; dt < CHUNK; dt++) {
            const int rd = dt & 1;
            float2 xv = *(const float2*)&x_sh[dt][0];
            float x0 = xv.x, x1 = xv.y;
            if (isl2) { x0 = h2_sh[0]; x1 = h2_sh[1]; }

            float av[NSEQ];
            {
                float gt0 = matvec(&hbuf[rd][0][0], fmaf(wi, x0, bias));
                float gt1 = matvec(&hbuf[rd][1][0], fmaf(wi, x1, bias));
                float th0 = tanhx(gg2 ? gt0 : 0.5f * gt0);
                float th1 = tanhx(gg2 ? gt1 : 0.5f * gt1);
                av[0] = gg2 ? th0 : fmaf(0.5f, th0, 0.5f);
                av[1] = gg2 ? th1 : fmaf(0.5f, th1, 0.5f);
            }
            // ---- gate exchange (nibble, dist 1/2/3) + cell update ------
            float af[NSEQ], ag[NSEQ], ao[NSEQ];
#pragma unroll
            for (int s = 0; s < NSEQ; s++) {
                af[s] = __shfl_down_sync(0xFFFFFFFFu, av[s], 1);
                ag[s] = __shfl_down_sync(0xFFFFFFFFu, av[s], 2);
                ao[s] = __shfl_down_sync(0xFFFFFFFFu, av[s], 3);
            }
            if (g0) {
                if (isl1) {
#pragma unroll
                    for (int s = 0; s < NSEQ; s++) {
                        cst[s] = fmaf(af[s], cst[s], av[s] * ag[s]);
                        float hv = ao[s] * tanhx(cst[s]);
                        ((__half*)&hbuf[1 - rd][s][0])[j] = __float2half_rn(hv);
                    }
                } else if (isl2 && (t0 | dt) != 0) {
#pragma unroll
                    for (int s = 0; s < NSEQ; s++) {
                        cst[s] = fmaf(af[s], cst[s], av[s] * ag[s]);
                        float y = ao[s] * tanhx(cst[s]);
                        ob_sh[s][dt] = y;
                        h2_sh[s] = y;
                    }
                }
            }
            __syncthreads();
        }
        // ---- flush outputs (lagged by 1) + stage next chunk ------------
        if (tid < 128) {
            int s = tid >> 6, col = tid & 63;
            int t = t0 - 1 + col;
            if (t >= 0) out[(n0 + s) * TT + t] = ob_sh[s][col];
        }
        if (t0 + CHUNK < TT && tid < 32) {
            int s = tid >> 4, q = (tid & 15) * 4;
            float4 v = *(const float4*)&stim[(n0 + s) * TT + t0 + CHUNK + q];
            x_sh[q + 0][s] = v.x; x_sh[q + 1][s] = v.y;
            x_sh[q + 2][s] = v.z; x_sh[q + 3][s] = v.w;
        }
        __syncthreads();
    }

    // ---- tail: y(2047) from h1(2047) (in hbuf[0]) ----------------------
    if (wid == 6) {
        float gt0 = matvec(&hbuf[0][0][0], fmaf(wi, h2_sh[0], bias));
        float gt1 = matvec(&hbuf[0][1][0], fmaf(wi, h2_sh[1], bias));
        float av[NSEQ];
        float th0 = tanhx(gg2 ? gt0 : 0.5f * gt0);
        float th1 = tanhx(gg2 ? gt1 : 0.5f * gt1);
        av[0] = gg2 ? th0 : fmaf(0.5f, th0, 0.5f);
        av[1] = gg2 ? th1 : fmaf(0.5f, th1, 0.5f);
#pragma unroll
        for (int s = 0; s < NSEQ; s++) {
            float af = __shfl_down_sync(0xFFFFFFFFu, av[s], 1);
            float ag = __shfl_down_sync(0xFFFFFFFFu, av[s], 2);
            float ao = __shfl_down_sync(0xFFFFFFFFu, av[s], 3);
            if (g0 && isl2) {
                cst[s] = fmaf(af, cst[s], av[s] * ag);
                out[(n0 + s) * TT + (TT - 1)] = ao * tanhx(cst[s]);
            }
        }
    }
}

extern "C" void kernel_launch(void* const* d_in, const int* in_sizes, int n_in,
                              void* d_out, int out_size)
{
    (void)in_sizes; (void)n_in; (void)out_size;
    const float* stim  = (const float*)d_in[0];
    const float* Wih1  = (const float*)d_in[1];
    const float* Whh1  = (const float*)d_in[2];
    const float* bih1  = (const float*)d_in[3];
    const float* bhh1  = (const float*)d_in[4];
    const float* Wih2  = (const float*)d_in[5];
    const float* Whh2  = (const float*)d_in[6];
    const float* bih2  = (const float*)d_in[7];
    const float* bhh2  = (const float*)d_in[8];
    float* out = (float*)d_out;

    lstm2_kernel<<<NN / NSEQ, NTHREADS>>>(stim, Wih1, Whh1, bih1, bhh1,
                                          Wih2, Whh2, bih2, bhh2, out);
}